// round 10
// baseline (speedup 1.0000x reference)
#include <cuda_runtime.h>
#include <cstdint>
#include <cstddef>

// ---------------- problem constants ----------------
#define PNUM 64
#define NP1  2048
#define M1c  512
#define M2c  128
#define KNB  32

#define INF_F  __int_as_float(0x7f800000)
#define NINF_F __int_as_float(0xff800000)

// ---------------- output layout (float32 concat of reference tuple) -------
#define OFF_XG      0          // 64*768
#define OFF_POSG    49152      // 64*3
#define OFF_BATCHG  49344      // 64
#define OFF_X2      49408      // 8192*384
#define OFF_Q2      3195136    // 8192*3
#define OFF_BATCH2  3219712    // 8192
#define OFF_VMIN    3227904    // 64*3
#define OFF_DIFF    3228096    // 64  (total 3228160)

// ---------------- scratch (__device__ globals; allocation-guard safe) -----
__device__ float g_pn  [PNUM*NP1*3];
__device__ float g_q1  [PNUM*M1c*3];
__device__ float g_q2  [PNUM*M2c*3];
__device__ int   g_nbr1[PNUM*M1c*KNB];
__device__ int   g_nbr2[PNUM*M2c*KNB];
__device__ float g_x1  [PNUM*M1c*128];
__device__ float g_feat[PNUM*M2c*KNB*136];   // 35.65M floats (L2 feat; L3 reuses)
__device__ float g_h   [PNUM*M2c*KNB*256];   // 67.1M floats (L2 hidden; L3 reuses)
__device__ float g_hb  [PNUM*M2c*768];       // L3 final pre-max (8192*768)
__device__ float g_w2a [136*256];
__device__ float g_w3a [392*512];

// exact (non-fma) squared distance, matching XLA's ((dx^2+dy^2)+dz^2)
__device__ __forceinline__ float d2f(float ax,float ay,float az,float bx,float by,float bz){
    float dx=__fadd_rn(ax,-bx), dy=__fadd_rn(ay,-by), dz=__fadd_rn(az,-bz);
    return __fadd_rn(__fadd_rn(__fmul_rn(dx,dx),__fmul_rn(dy,dy)),__fmul_rn(dz,dz));
}

// ---------------- normalize: per-patch min/max, pn = (p - vmin)/diff -------
__global__ void k_norm(const float* __restrict__ pos, float* __restrict__ out)
{
    const int p = blockIdx.x, t = threadIdx.x;
    __shared__ float smn[3*256], smx[3*256];
    __shared__ float svm[3]; __shared__ float sdf;
    float mn0=INF_F, mn1=INF_F, mn2=INF_F, mx0=NINF_F, mx1=NINF_F, mx2=NINF_F;
    const float* pp = pos + (size_t)p * NP1 * 3;
    for (int i = t; i < NP1; i += 256) {
        float x = pp[i*3+0], y = pp[i*3+1], z = pp[i*3+2];
        mn0 = fminf(mn0,x); mn1 = fminf(mn1,y); mn2 = fminf(mn2,z);
        mx0 = fmaxf(mx0,x); mx1 = fmaxf(mx1,y); mx2 = fmaxf(mx2,z);
    }
    smn[t]=mn0; smn[256+t]=mn1; smn[512+t]=mn2;
    smx[t]=mx0; smx[256+t]=mx1; smx[512+t]=mx2;
    __syncthreads();
    for (int s = 128; s > 0; s >>= 1) {
        if (t < s) {
            #pragma unroll
            for (int c = 0; c < 3; c++) {
                smn[c*256+t] = fminf(smn[c*256+t], smn[c*256+t+s]);
                smx[c*256+t] = fmaxf(smx[c*256+t], smx[c*256+t+s]);
            }
        }
        __syncthreads();
    }
    if (t == 0) {
        float d0 = smx[0]-smn[0], d1 = smx[256]-smn[256], d2 = smx[512]-smn[512];
        float df = fmaxf(d0, fmaxf(d1, d2));
        svm[0]=smn[0]; svm[1]=smn[256]; svm[2]=smn[512]; sdf = df;
        out[OFF_VMIN + p*3+0] = smn[0];
        out[OFF_VMIN + p*3+1] = smn[256];
        out[OFF_VMIN + p*3+2] = smn[512];
        out[OFF_DIFF + p] = df;
    }
    __syncthreads();
    const float vx=svm[0], vy=svm[1], vz=svm[2], df=sdf;
    for (int i = t; i < NP1; i += 256) {
        size_t b = ((size_t)p*NP1 + i)*3;
        g_pn[b+0] = __fdiv_rn(__fadd_rn(pp[i*3+0],-vx), df);
        g_pn[b+1] = __fdiv_rn(__fadd_rn(pp[i*3+1],-vy), df);
        g_pn[b+2] = __fdiv_rn(__fadd_rn(pp[i*3+2],-vz), df);
    }
}

// ---------------- aux: pad weights, write constant output regions ----------
__global__ void k_aux(const float* __restrict__ W2a, const float* __restrict__ W3a,
                      float* __restrict__ out)
{
    int tid = blockIdx.x*256 + threadIdx.x;
    if (tid < 136*256)  g_w2a[tid] = (tid < 131*256) ? W2a[tid] : 0.f;
    if (tid < 392*512)  g_w3a[tid] = (tid < 387*512) ? W3a[tid] : 0.f;
    if (tid < 192)      out[OFF_POSG + tid] = 0.f;
    if (tid < 64)       out[OFF_BATCHG + tid] = (float)tid;
    if (tid < PNUM*M2c) out[OFF_BATCH2 + tid] = (float)(tid / M2c);
}

// ---------------- FPS (sequential, shared-memory resident) -----------------
template<int NP, int MS>
__global__ void k_fps(const float* __restrict__ pts,
                      float* __restrict__ q_out, float* __restrict__ q_out2)
{
    const int p = blockIdx.x, t = threadIdx.x;
    const int lane = t & 31, wid = t >> 5;
    __shared__ float sx[NP], sy[NP], sz[NP], sd[NP];
    __shared__ float rv[8]; __shared__ int ri[8];
    __shared__ int ssel[MS]; __shared__ int sj;
    const float* pp = pts + (size_t)p * NP * 3;
    for (int i = t; i < NP; i += 256) { sx[i]=pp[i*3]; sy[i]=pp[i*3+1]; sz[i]=pp[i*3+2]; }
    __syncthreads();
    const float x0 = sx[0], y0 = sy[0], z0 = sz[0];
    for (int i = t; i < NP; i += 256)
        sd[i] = d2f(sx[i],sy[i],sz[i], x0,y0,z0);
    if (t == 0) ssel[0] = 0;
    __syncthreads();
    for (int s = 1; s < MS; s++) {
        float bv = -1.0f; int bi = 0;
        for (int i = t; i < NP; i += 256) { float v = sd[i]; if (v > bv) { bv = v; bi = i; } }
        #pragma unroll
        for (int o = 16; o > 0; o >>= 1) {
            float ov = __shfl_down_sync(0xffffffffu, bv, o);
            int   oi = __shfl_down_sync(0xffffffffu, bi, o);
            if (ov > bv || (ov == bv && oi < bi)) { bv = ov; bi = oi; }
        }
        if (lane == 0) { rv[wid] = bv; ri[wid] = bi; }
        __syncthreads();
        if (t == 0) {
            float v = rv[0]; int b = ri[0];
            #pragma unroll
            for (int w = 1; w < 8; w++)
                if (rv[w] > v || (rv[w] == v && ri[w] < b)) { v = rv[w]; b = ri[w]; }
            sj = b; ssel[s] = b;
        }
        __syncthreads();
        const int j = sj;
        const float jx = sx[j], jy = sy[j], jz = sz[j];
        for (int i = t; i < NP; i += 256)
            sd[i] = fminf(sd[i], d2f(sx[i],sy[i],sz[i], jx,jy,jz));
        __syncthreads();
    }
    for (int m = t; m < MS; m += 256) {
        int j = ssel[m];
        size_t qb = ((size_t)p*MS + m)*3;
        float qx=sx[j], qy=sy[j], qz=sz[j];
        q_out[qb+0]=qx; q_out[qb+1]=qy; q_out[qb+2]=qz;
        if (q_out2) { q_out2[qb+0]=qx; q_out2[qb+1]=qy; q_out2[qb+2]=qz; }
    }
}

// ---------------- warp top-K(32) within radius, bitonic merge --------------
__device__ __forceinline__ bool pless(float d, int i, float od, int oi)
{
    return d < od || (d == od && i < oi);
}

template<int NP>
__global__ void k_select(const float* __restrict__ pts, const float* __restrict__ q,
                         int* __restrict__ nbr, float r2, int M)
{
    const int grpPerPatch = M / 8;
    const int p   = blockIdx.x / grpPerPatch;
    const int grp = blockIdx.x % grpPerPatch;
    const int t = threadIdx.x, lane = t & 31, w = t >> 5;
    __shared__ float sx[NP], sy[NP], sz[NP];
    const float* pp = pts + (size_t)p * NP * 3;
    for (int i = t; i < NP; i += 256) { sx[i]=pp[i*3]; sy[i]=pp[i*3+1]; sz[i]=pp[i*3+2]; }
    __syncthreads();
    const int m = grp*8 + w;
    const int cent = p*M + m;
    const float qx = q[cent*3], qy = q[cent*3+1], qz = q[cent*3+2];
    float cd = INF_F; int ci = 0x7fffff00 + lane;   // (inf, big distinct idx) pads, asc
    for (int nb = 0; nb < NP/32; nb++) {
        const int j = nb*32 + lane;
        float d2 = d2f(sx[j],sy[j],sz[j], qx,qy,qz);
        float nd = (d2 <= r2) ? d2 : INF_F;
        int   ni = j;
        float td = __shfl_sync(0xffffffffu, cd, 31);
        if (__any_sync(0xffffffffu, nd < td)) {
            #pragma unroll
            for (int size = 2; size <= 32; size <<= 1) {
                #pragma unroll
                for (int stride = size >> 1; stride > 0; stride >>= 1) {
                    float od = __shfl_xor_sync(0xffffffffu, nd, stride);
                    int   oi = __shfl_xor_sync(0xffffffffu, ni, stride);
                    bool up    = ((lane & size) == 0);
                    bool lower = ((lane & stride) == 0);
                    bool ls = pless(nd, ni, od, oi);
                    bool take = (lower == up) ? !ls : ls;
                    if (take) { nd = od; ni = oi; }
                }
            }
            float rd = __shfl_sync(0xffffffffu, nd, 31 - lane);
            int   rx = __shfl_sync(0xffffffffu, ni, 31 - lane);
            if (pless(rd, rx, cd, ci)) { cd = rd; ci = rx; }
            #pragma unroll
            for (int stride = 16; stride > 0; stride >>= 1) {
                float od = __shfl_xor_sync(0xffffffffu, cd, stride);
                int   oi = __shfl_xor_sync(0xffffffffu, ci, stride);
                bool lower = ((lane & stride) == 0);
                bool ls = pless(cd, ci, od, oi);
                bool take = lower ? !ls : ls;
                if (take) { cd = od; ci = oi; }
            }
        }
    }
    nbr[cent*KNB + lane] = (cd <= r2) ? ci : -1;
}

// ---------------- fused layer 1: gather + MLP(6->64->128) + masked max -----
// one block = 2 centroids = 64 neighbor rows; K=64 fits in one tile.
__global__ void __launch_bounds__(256) k_l1_fused(
    const float* __restrict__ W1a, const float* __restrict__ b1a,
    const float* __restrict__ W1b, const float* __restrict__ b1b)
{
    __shared__ float sW[64*128];   // W1b (k-major rows x 128 cols), 32KB
    __shared__ float sA[64*64];    // h1, layout [k][row], 16KB (reused for partials)
    const int t = threadIdx.x;
    const int cent0 = blockIdx.x * 2;
    const int p = cent0 >> 9;                 // /512
    {
        const float4* wsrc = (const float4*)W1b;
        float4* wdst = (float4*)sW;
        #pragma unroll
        for (int i = 0; i < 8; i++) wdst[t + i*256] = wsrc[t + i*256];
    }
    {
        const int row = t >> 2;
        const int c0 = (t & 3) * 16;
        const int cent = cent0 + (row >> 5);
        const int j = g_nbr1[cent*KNB + (row & 31)];
        float f0=0,f1=0,f2=0,f3=0,f4=0,f5=0;
        if (j >= 0) {
            size_t pb = ((size_t)p*NP1 + j)*3;
            f0 = g_pn[pb]; f1 = g_pn[pb+1]; f2 = g_pn[pb+2];
            f3 = __fadd_rn(f0, -g_q1[cent*3]);
            f4 = __fadd_rn(f1, -g_q1[cent*3+1]);
            f5 = __fadd_rn(f2, -g_q1[cent*3+2]);
        }
        #pragma unroll
        for (int c = 0; c < 16; c++) {
            float acc = b1a[c0+c];
            acc += f0*W1a[0*64+c0+c]; acc += f1*W1a[1*64+c0+c];
            acc += f2*W1a[2*64+c0+c]; acc += f3*W1a[3*64+c0+c];
            acc += f4*W1a[4*64+c0+c]; acc += f5*W1a[5*64+c0+c];
            sA[(c0+c)*64 + row] = fmaxf(acc, 0.f);
        }
    }
    __syncthreads();
    const int tx = t & 15, ty = t >> 4;       // cols tx*8.., rows ty*4..
    float acc[4][8] = {};
    #pragma unroll 4
    for (int k = 0; k < 64; k++) {
        float4 a  = *(const float4*)&sA[k*64 + ty*4];
        float4 b0 = *(const float4*)&sW[k*128 + tx*8];
        float4 b1 = *(const float4*)&sW[k*128 + tx*8 + 4];
        float av[4] = {a.x,a.y,a.z,a.w};
        float bv[8] = {b0.x,b0.y,b0.z,b0.w,b1.x,b1.y,b1.z,b1.w};
        #pragma unroll
        for (int i=0;i<4;i++)
            #pragma unroll
            for (int jj=0;jj<8;jj++)
                acc[i][jj] += av[i]*bv[jj];
    }
    __syncthreads();
    float pm[8];
    #pragma unroll
    for (int jj=0;jj<8;jj++) pm[jj] = NINF_F;
    #pragma unroll
    for (int i=0;i<4;i++) {
        int row = ty*4 + i;
        int cent = cent0 + (row >> 5);
        if (g_nbr1[cent*KNB + (row & 31)] >= 0) {
            #pragma unroll
            for (int jj=0;jj<8;jj++)
                pm[jj] = fmaxf(pm[jj], fmaxf(acc[i][jj] + b1b[tx*8+jj], 0.f));
        }
    }
    #pragma unroll
    for (int jj=0;jj<8;jj++) sA[ty*128 + tx*8 + jj] = pm[jj];
    __syncthreads();
    {
        int cent = t >> 7;                    // 0..1
        int col  = t & 127;
        float v = NINF_F;
        #pragma unroll
        for (int g = 0; g < 8; g++)
            v = fmaxf(v, sA[(cent*8+g)*128 + col]);
        g_x1[(size_t)(cent0+cent)*128 + col] = v;
    }
}

// ---------------- gather / feature build (layers 2 & 3) --------------------
__global__ void k_gather2()
{
    int row = blockIdx.x*8 + (threadIdx.x >> 5);   // warp per row, [0, 262144)
    int lane = threadIdx.x & 31;
    if (row >= PNUM*M2c*KNB) return;
    int cent = row >> 5;                            // [0, 8192)
    int p = cent >> 7;                              // cent / 128
    int j = g_nbr2[row];
    float qx = g_q2[cent*3], qy = g_q2[cent*3+1], qz = g_q2[cent*3+2];
    for (int c = lane; c < 136; c += 32) {
        float v = 0.f;
        if (j >= 0) {
            if (c < 128)        v = g_x1[((size_t)(p*M1c + j))*128 + c];
            else if (c == 128)  v = __fadd_rn(g_q1[(p*M1c+j)*3+0], -qx);
            else if (c == 129)  v = __fadd_rn(g_q1[(p*M1c+j)*3+1], -qy);
            else if (c == 130)  v = __fadd_rn(g_q1[(p*M1c+j)*3+2], -qz);
        }
        g_feat[(size_t)row*136 + c] = v;
    }
}

__global__ void k_gather3(const float* __restrict__ out)
{
    int tid = blockIdx.x*256 + threadIdx.x;
    if (tid >= PNUM*M2c*392) return;
    int r = tid / 392, c = tid - r*392;
    float v = 0.f;
    if (c < 384)      v = out[OFF_X2 + (size_t)r*384 + c];
    else if (c < 387) v = g_q2[r*3 + (c-384)];
    g_feat[(size_t)r*392 + c] = v;
}

// ------- SGEMM: relu(A@W+b), 128x64 tile, BK=8, 8x4 micro, prefetched -----
__global__ void __launch_bounds__(256) k_gemm_relu(
    const float* __restrict__ A, const float* __restrict__ W,
    const float* __restrict__ bias, float* __restrict__ C,
    int M, int N, int K)
{
    __shared__ float As[8][128];
    __shared__ float Bs[8][64];
    const int ntile = N >> 6;
    const int bx = blockIdx.x % ntile;
    const int by = blockIdx.x / ntile;
    const int t = threadIdx.x;
    const int tx = t & 15, ty = t >> 4;
    const int row0 = by*128, col0 = bx*64;
    float acc[8][4] = {};
    const int ar = t >> 1, ac = (t & 1) * 4;
    const int br = t >> 5, bc = (t & 31) * 2;
    const float* Aptr = A + (size_t)(row0 + ar)*K + ac;
    const float* Wptr = W + (size_t)br*N + col0 + bc;
    float4 av = *(const float4*)(Aptr);
    float2 bv = *(const float2*)(Wptr);
    for (int k0 = 0; k0 < K; k0 += 8) {
        As[ac][ar] = av.x; As[ac+1][ar] = av.y; As[ac+2][ar] = av.z; As[ac+3][ar] = av.w;
        Bs[br][bc] = bv.x; Bs[br][bc+1] = bv.y;
        __syncthreads();
        if (k0 + 8 < K) {
            av = *(const float4*)(Aptr + k0 + 8);
            bv = *(const float2*)(Wptr + (size_t)(k0 + 8)*N);
        }
        #pragma unroll
        for (int kk = 0; kk < 8; kk++) {
            float4 a0 = *(const float4*)&As[kk][ty*8];
            float4 a1 = *(const float4*)&As[kk][ty*8 + 4];
            float4 b  = *(const float4*)&Bs[kk][tx*4];
            float av8[8] = {a0.x,a0.y,a0.z,a0.w,a1.x,a1.y,a1.z,a1.w};
            float bv4[4] = {b.x,b.y,b.z,b.w};
            #pragma unroll
            for (int i = 0; i < 8; i++)
                #pragma unroll
                for (int jj = 0; jj < 4; jj++)
                    acc[i][jj] += av8[i]*bv4[jj];
        }
        __syncthreads();
    }
    #pragma unroll
    for (int i = 0; i < 8; i++) {
        int r = row0 + ty*8 + i;
        #pragma unroll
        for (int jj = 0; jj < 4; jj++) {
            int c = col0 + tx*4 + jj;
            C[(size_t)r*N + c] = fmaxf(acc[i][jj] + bias[c], 0.f);
        }
    }
}

// -- L2 second GEMM fused with masked neighbor-max (128 rows = 4 centroids) -
__global__ void __launch_bounds__(256) k_gemm2_max(
    const float* __restrict__ A, const float* __restrict__ W,
    const float* __restrict__ bias, float* __restrict__ out)
{
    // M=262144, N=384, K=256
    __shared__ float As[8][128];
    __shared__ float Bs[8][64];
    __shared__ float sT[128][65];
    const int ntile = 6;
    const int bx = blockIdx.x % ntile;
    const int by = blockIdx.x / ntile;
    const int t = threadIdx.x;
    const int tx = t & 15, ty = t >> 4;
    const int row0 = by*128, col0 = bx*64;
    const int N = 384, K = 256;
    float acc[8][4] = {};
    const int ar = t >> 1, ac = (t & 1) * 4;
    const int br = t >> 5, bc = (t & 31) * 2;
    const float* Aptr = A + (size_t)(row0 + ar)*K + ac;
    const float* Wptr = W + (size_t)br*N + col0 + bc;
    float4 av = *(const float4*)(Aptr);
    float2 bv = *(const float2*)(Wptr);
    for (int k0 = 0; k0 < K; k0 += 8) {
        As[ac][ar] = av.x; As[ac+1][ar] = av.y; As[ac+2][ar] = av.z; As[ac+3][ar] = av.w;
        Bs[br][bc] = bv.x; Bs[br][bc+1] = bv.y;
        __syncthreads();
        if (k0 + 8 < K) {
            av = *(const float4*)(Aptr + k0 + 8);
            bv = *(const float2*)(Wptr + (size_t)(k0 + 8)*N);
        }
        #pragma unroll
        for (int kk = 0; kk < 8; kk++) {
            float4 a0 = *(const float4*)&As[kk][ty*8];
            float4 a1 = *(const float4*)&As[kk][ty*8 + 4];
            float4 b  = *(const float4*)&Bs[kk][tx*4];
            float av8[8] = {a0.x,a0.y,a0.z,a0.w,a1.x,a1.y,a1.z,a1.w};
            float bv4[4] = {b.x,b.y,b.z,b.w};
            #pragma unroll
            for (int i = 0; i < 8; i++)
                #pragma unroll
                for (int jj = 0; jj < 4; jj++)
                    acc[i][jj] += av8[i]*bv4[jj];
        }
        __syncthreads();
    }
    #pragma unroll
    for (int i = 0; i < 8; i++)
        #pragma unroll
        for (int jj = 0; jj < 4; jj++)
            sT[ty*8+i][tx*4+jj] = fmaxf(acc[i][jj] + bias[col0 + tx*4+jj], 0.f);
    __syncthreads();
    {
        int cent = t >> 6, col = t & 63;      // 4 centroids x 64 cols = 256 threads
        int gcent = by*4 + cent;
        float v = NINF_F;
        #pragma unroll 4
        for (int k = 0; k < KNB; k++)
            if (g_nbr2[gcent*KNB + k] >= 0)
                v = fmaxf(v, sT[cent*32+k][col]);
        out[OFF_X2 + (size_t)gcent*384 + col0 + col] = v;
    }
}

// ---------------- global max over centroids (layer 3) ----------------------
__global__ void k_max3(float* __restrict__ out)
{
    int tid = blockIdx.x*256 + threadIdx.x;        // < 64*768
    if (tid >= PNUM*768) return;
    int p = tid / 768, c = tid - p*768;
    float v = NINF_F;
    for (int m = 0; m < M2c; m++)
        v = fmaxf(v, g_hb[((size_t)p*M2c + m)*768 + c]);
    out[OFF_XG + tid] = v;
}

// ---------------- launcher --------------------------------------------------
static void launch_gemm(const float* A, const float* W, const float* b, float* C,
                        int M, int N, int K)
{
    int blocks = (M/128) * (N/64);
    k_gemm_relu<<<blocks, 256>>>(A, W, b, C, M, N, K);
}

extern "C" void kernel_launch(void* const* d_in, const int* in_sizes, int n_in,
                              void* d_out, int out_size)
{
    const float* pos = (const float*)d_in[0];
    const float* W1a = (const float*)d_in[2];
    const float* b1a = (const float*)d_in[3];
    const float* W1b = (const float*)d_in[4];
    const float* b1b = (const float*)d_in[5];
    const float* W2a = (const float*)d_in[6];
    const float* b2a = (const float*)d_in[7];
    const float* W2b = (const float*)d_in[8];
    const float* b2b = (const float*)d_in[9];
    const float* W3a = (const float*)d_in[10];
    const float* b3a = (const float*)d_in[11];
    const float* W3b = (const float*)d_in[12];
    const float* b3b = (const float*)d_in[13];
    float* out = (float*)d_out;

    float *pn, *q1, *q2, *feat, *h, *hb, *w2a, *w3a;
    int *nbr1, *nbr2;
    cudaGetSymbolAddress((void**)&pn,   g_pn);
    cudaGetSymbolAddress((void**)&q1,   g_q1);
    cudaGetSymbolAddress((void**)&q2,   g_q2);
    cudaGetSymbolAddress((void**)&feat, g_feat);
    cudaGetSymbolAddress((void**)&h,    g_h);
    cudaGetSymbolAddress((void**)&hb,   g_hb);
    cudaGetSymbolAddress((void**)&w2a,  g_w2a);
    cudaGetSymbolAddress((void**)&w3a,  g_w3a);
    cudaGetSymbolAddress((void**)&nbr1, g_nbr1);
    cudaGetSymbolAddress((void**)&nbr2, g_nbr2);

    // stage 0: normalize + constants + padded weights
    k_norm<<<PNUM, 256>>>(pos, out);
    k_aux<<<(392*512 + 255)/256, 256>>>(W2a, W3a, out);

    // layer 1: FPS -> radius top-K -> fused gather+MLP+max
    k_fps<NP1, M1c><<<PNUM, 256>>>(pn, q1, nullptr);
    k_select<NP1><<<PNUM*M1c/8, 256>>>(pn, q1, nbr1, 0.0225f, M1c);
    k_l1_fused<<<PNUM*M1c/2, 256>>>(W1a, b1a, W1b, b1b);

    // layer 2
    k_fps<M1c, M2c><<<PNUM, 256>>>(q1, q2, out + OFF_Q2);
    k_select<M1c><<<PNUM*M2c/8, 256>>>(q1, q2, nbr2, 0.09f, M2c);
    k_gather2<<<PNUM*M2c*KNB/8, 256>>>();
    launch_gemm(feat, w2a, b2a, h, PNUM*M2c*KNB, 256, 136);
    k_gemm2_max<<<(PNUM*M2c*KNB/128)*6, 256>>>(h, W2b, b2b, out);

    // layer 3
    k_gather3<<<(PNUM*M2c*392 + 255)/256, 256>>>(out);
    launch_gemm(feat, w3a, b3a, h,  PNUM*M2c, 512, 392);
    launch_gemm(h,    W3b, b3b, hb, PNUM*M2c, 768, 512);
    k_max3<<<(PNUM*768 + 255)/256, 256>>>(out);
}

// round 14
// speedup vs baseline: 1.0052x; 1.0052x over previous
#include <cuda_runtime.h>
#include <cstdint>
#include <cstddef>

// ---------------- problem constants ----------------
#define PNUM 64
#define NP1  2048
#define M1c  512
#define M2c  128
#define KNB  32

#define INF_F  __int_as_float(0x7f800000)
#define NINF_F __int_as_float(0xff800000)

// ---------------- output layout (float32 concat of reference tuple) -------
#define OFF_XG      0          // 64*768
#define OFF_POSG    49152      // 64*3
#define OFF_BATCHG  49344      // 64
#define OFF_X2      49408      // 8192*384
#define OFF_Q2      3195136    // 8192*3
#define OFF_BATCH2  3219712    // 8192
#define OFF_VMIN    3227904    // 64*3
#define OFF_DIFF    3228096    // 64  (total 3228160)

// ---------------- scratch (__device__ globals; allocation-guard safe) -----
__device__ float g_pn  [PNUM*NP1*3];
__device__ float g_q1  [PNUM*M1c*3];
__device__ float g_q2  [PNUM*M2c*3];
__device__ int   g_nbr1[PNUM*M1c*KNB];
__device__ int   g_nbr2[PNUM*M2c*KNB];
__device__ float g_x1  [PNUM*M1c*128];
__device__ float g_feat[PNUM*M2c*KNB*136];   // L2 feat; L3 reuses
__device__ float g_h   [PNUM*M2c*KNB*256];   // L2 hidden; L3 reuses
__device__ float g_hb  [PNUM*M2c*768];       // L3 final pre-max
__device__ float g_w2a [136*256];
__device__ float g_w3a [392*512];

// exact (non-fma) squared distance, matching XLA's ((dx^2+dy^2)+dz^2)
__device__ __forceinline__ float d2f(float ax,float ay,float az,float bx,float by,float bz){
    float dx=__fadd_rn(ax,-bx), dy=__fadd_rn(ay,-by), dz=__fadd_rn(az,-bz);
    return __fadd_rn(__fadd_rn(__fmul_rn(dx,dx),__fmul_rn(dy,dy)),__fmul_rn(dz,dz));
}

// ---------------- normalize: per-patch min/max, pn = (p - vmin)/diff -------
__global__ void k_norm(const float* __restrict__ pos, float* __restrict__ out)
{
    const int p = blockIdx.x, t = threadIdx.x;
    __shared__ float smn[3*256], smx[3*256];
    __shared__ float svm[3]; __shared__ float sdf;
    float mn0=INF_F, mn1=INF_F, mn2=INF_F, mx0=NINF_F, mx1=NINF_F, mx2=NINF_F;
    const float* pp = pos + (size_t)p * NP1 * 3;
    for (int i = t; i < NP1; i += 256) {
        float x = pp[i*3+0], y = pp[i*3+1], z = pp[i*3+2];
        mn0 = fminf(mn0,x); mn1 = fminf(mn1,y); mn2 = fminf(mn2,z);
        mx0 = fmaxf(mx0,x); mx1 = fmaxf(mx1,y); mx2 = fmaxf(mx2,z);
    }
    smn[t]=mn0; smn[256+t]=mn1; smn[512+t]=mn2;
    smx[t]=mx0; smx[256+t]=mx1; smx[512+t]=mx2;
    __syncthreads();
    for (int s = 128; s > 0; s >>= 1) {
        if (t < s) {
            #pragma unroll
            for (int c = 0; c < 3; c++) {
                smn[c*256+t] = fminf(smn[c*256+t], smn[c*256+t+s]);
                smx[c*256+t] = fmaxf(smx[c*256+t], smx[c*256+t+s]);
            }
        }
        __syncthreads();
    }
    if (t == 0) {
        float d0 = smx[0]-smn[0], d1 = smx[256]-smn[256], d2 = smx[512]-smn[512];
        float df = fmaxf(d0, fmaxf(d1, d2));
        svm[0]=smn[0]; svm[1]=smn[256]; svm[2]=smn[512]; sdf = df;
        out[OFF_VMIN + p*3+0] = smn[0];
        out[OFF_VMIN + p*3+1] = smn[256];
        out[OFF_VMIN + p*3+2] = smn[512];
        out[OFF_DIFF + p] = df;
    }
    __syncthreads();
    const float vx=svm[0], vy=svm[1], vz=svm[2], df=sdf;
    for (int i = t; i < NP1; i += 256) {
        size_t b = ((size_t)p*NP1 + i)*3;
        g_pn[b+0] = __fdiv_rn(__fadd_rn(pp[i*3+0],-vx), df);
        g_pn[b+1] = __fdiv_rn(__fadd_rn(pp[i*3+1],-vy), df);
        g_pn[b+2] = __fdiv_rn(__fadd_rn(pp[i*3+2],-vz), df);
    }
}

// ---------------- aux: pad weights, write constant output regions ----------
__global__ void k_aux(const float* __restrict__ W2a, const float* __restrict__ W3a,
                      float* __restrict__ out)
{
    int tid = blockIdx.x*256 + threadIdx.x;
    if (tid < 136*256)  g_w2a[tid] = (tid < 131*256) ? W2a[tid] : 0.f;
    if (tid < 392*512)  g_w3a[tid] = (tid < 387*512) ? W3a[tid] : 0.f;
    if (tid < 192)      out[OFF_POSG + tid] = 0.f;
    if (tid < 64)       out[OFF_BATCHG + tid] = (float)tid;
    if (tid < PNUM*M2c) out[OFF_BATCH2 + tid] = (float)(tid / M2c);
}

// ---------------- FPS (sequential, shared-memory resident) -----------------
template<int NP, int MS>
__global__ void k_fps(const float* __restrict__ pts,
                      float* __restrict__ q_out, float* __restrict__ q_out2)
{
    const int p = blockIdx.x, t = threadIdx.x;
    const int lane = t & 31, wid = t >> 5;
    __shared__ float sx[NP], sy[NP], sz[NP], sd[NP];
    __shared__ float rv[8]; __shared__ int ri[8];
    __shared__ int ssel[MS]; __shared__ int sj;
    const float* pp = pts + (size_t)p * NP * 3;
    for (int i = t; i < NP; i += 256) { sx[i]=pp[i*3]; sy[i]=pp[i*3+1]; sz[i]=pp[i*3+2]; }
    __syncthreads();
    const float x0 = sx[0], y0 = sy[0], z0 = sz[0];
    for (int i = t; i < NP; i += 256)
        sd[i] = d2f(sx[i],sy[i],sz[i], x0,y0,z0);
    if (t == 0) ssel[0] = 0;
    __syncthreads();
    for (int s = 1; s < MS; s++) {
        float bv = -1.0f; int bi = 0;
        for (int i = t; i < NP; i += 256) { float v = sd[i]; if (v > bv) { bv = v; bi = i; } }
        #pragma unroll
        for (int o = 16; o > 0; o >>= 1) {
            float ov = __shfl_down_sync(0xffffffffu, bv, o);
            int   oi = __shfl_down_sync(0xffffffffu, bi, o);
            if (ov > bv || (ov == bv && oi < bi)) { bv = ov; bi = oi; }
        }
        if (lane == 0) { rv[wid] = bv; ri[wid] = bi; }
        __syncthreads();
        if (t == 0) {
            float v = rv[0]; int b = ri[0];
            #pragma unroll
            for (int w = 1; w < 8; w++)
                if (rv[w] > v || (rv[w] == v && ri[w] < b)) { v = rv[w]; b = ri[w]; }
            sj = b; ssel[s] = b;
        }
        __syncthreads();
        const int j = sj;
        const float jx = sx[j], jy = sy[j], jz = sz[j];
        for (int i = t; i < NP; i += 256)
            sd[i] = fminf(sd[i], d2f(sx[i],sy[i],sz[i], jx,jy,jz));
        __syncthreads();
    }
    for (int m = t; m < MS; m += 256) {
        int j = ssel[m];
        size_t qb = ((size_t)p*MS + m)*3;
        float qx=sx[j], qy=sy[j], qz=sz[j];
        q_out[qb+0]=qx; q_out[qb+1]=qy; q_out[qb+2]=qz;
        if (q_out2) { q_out2[qb+0]=qx; q_out2[qb+1]=qy; q_out2[qb+2]=qz; }
    }
}

// ---------------- warp top-K(32) within radius, bitonic merge --------------
__device__ __forceinline__ bool pless(float d, int i, float od, int oi)
{
    return d < od || (d == od && i < oi);
}

template<int NP>
__global__ void k_select(const float* __restrict__ pts, const float* __restrict__ q,
                         int* __restrict__ nbr, float r2, int M)
{
    const int grpPerPatch = M / 8;
    const int p   = blockIdx.x / grpPerPatch;
    const int grp = blockIdx.x % grpPerPatch;
    const int t = threadIdx.x, lane = t & 31, w = t >> 5;
    __shared__ float sx[NP], sy[NP], sz[NP];
    const float* pp = pts + (size_t)p * NP * 3;
    for (int i = t; i < NP; i += 256) { sx[i]=pp[i*3]; sy[i]=pp[i*3+1]; sz[i]=pp[i*3+2]; }
    __syncthreads();
    const int m = grp*8 + w;
    const int cent = p*M + m;
    const float qx = q[cent*3], qy = q[cent*3+1], qz = q[cent*3+2];
    float cd = INF_F; int ci = 0x7fffff00 + lane;   // (inf, big distinct idx) pads, asc
    for (int nb = 0; nb < NP/32; nb++) {
        const int j = nb*32 + lane;
        float d2 = d2f(sx[j],sy[j],sz[j], qx,qy,qz);
        float nd = (d2 <= r2) ? d2 : INF_F;
        int   ni = j;
        float td = __shfl_sync(0xffffffffu, cd, 31);
        if (__any_sync(0xffffffffu, nd < td)) {
            #pragma unroll
            for (int size = 2; size <= 32; size <<= 1) {
                #pragma unroll
                for (int stride = size >> 1; stride > 0; stride >>= 1) {
                    float od = __shfl_xor_sync(0xffffffffu, nd, stride);
                    int   oi = __shfl_xor_sync(0xffffffffu, ni, stride);
                    bool up    = ((lane & size) == 0);
                    bool lower = ((lane & stride) == 0);
                    bool ls = pless(nd, ni, od, oi);
                    bool take = (lower == up) ? !ls : ls;
                    if (take) { nd = od; ni = oi; }
                }
            }
            float rd = __shfl_sync(0xffffffffu, nd, 31 - lane);
            int   rx = __shfl_sync(0xffffffffu, ni, 31 - lane);
            if (pless(rd, rx, cd, ci)) { cd = rd; ci = rx; }
            #pragma unroll
            for (int stride = 16; stride > 0; stride >>= 1) {
                float od = __shfl_xor_sync(0xffffffffu, cd, stride);
                int   oi = __shfl_xor_sync(0xffffffffu, ci, stride);
                bool lower = ((lane & stride) == 0);
                bool ls = pless(cd, ci, od, oi);
                bool take = lower ? !ls : ls;
                if (take) { cd = od; ci = oi; }
            }
        }
    }
    nbr[cent*KNB + lane] = (cd <= r2) ? ci : -1;
}

// ---------------- fused layer 1: gather + MLP(6->64->128) + masked max -----
__global__ void __launch_bounds__(256) k_l1_fused(
    const float* __restrict__ W1a, const float* __restrict__ b1a,
    const float* __restrict__ W1b, const float* __restrict__ b1b)
{
    __shared__ float sW[64*128];   // W1b, 32KB
    __shared__ float sA[64*64];    // h1 [k][row], 16KB (reused for partials)
    const int t = threadIdx.x;
    const int cent0 = blockIdx.x * 2;
    const int p = cent0 >> 9;
    {
        const float4* wsrc = (const float4*)W1b;
        float4* wdst = (float4*)sW;
        #pragma unroll
        for (int i = 0; i < 8; i++) wdst[t + i*256] = wsrc[t + i*256];
    }
    {
        const int row = t >> 2;
        const int c0 = (t & 3) * 16;
        const int cent = cent0 + (row >> 5);
        const int j = g_nbr1[cent*KNB + (row & 31)];
        float f0=0,f1=0,f2=0,f3=0,f4=0,f5=0;
        if (j >= 0) {
            size_t pb = ((size_t)p*NP1 + j)*3;
            f0 = g_pn[pb]; f1 = g_pn[pb+1]; f2 = g_pn[pb+2];
            f3 = __fadd_rn(f0, -g_q1[cent*3]);
            f4 = __fadd_rn(f1, -g_q1[cent*3+1]);
            f5 = __fadd_rn(f2, -g_q1[cent*3+2]);
        }
        #pragma unroll
        for (int c = 0; c < 16; c++) {
            float acc = b1a[c0+c];
            acc += f0*W1a[0*64+c0+c]; acc += f1*W1a[1*64+c0+c];
            acc += f2*W1a[2*64+c0+c]; acc += f3*W1a[3*64+c0+c];
            acc += f4*W1a[4*64+c0+c]; acc += f5*W1a[5*64+c0+c];
            sA[(c0+c)*64 + row] = fmaxf(acc, 0.f);
        }
    }
    __syncthreads();
    const int tx = t & 15, ty = t >> 4;
    float acc[4][8] = {};
    #pragma unroll 4
    for (int k = 0; k < 64; k++) {
        float4 a  = *(const float4*)&sA[k*64 + ty*4];
        float4 b0 = *(const float4*)&sW[k*128 + tx*8];
        float4 b1 = *(const float4*)&sW[k*128 + tx*8 + 4];
        float av[4] = {a.x,a.y,a.z,a.w};
        float bv[8] = {b0.x,b0.y,b0.z,b0.w,b1.x,b1.y,b1.z,b1.w};
        #pragma unroll
        for (int i=0;i<4;i++)
            #pragma unroll
            for (int jj=0;jj<8;jj++)
                acc[i][jj] += av[i]*bv[jj];
    }
    __syncthreads();
    float pm[8];
    #pragma unroll
    for (int jj=0;jj<8;jj++) pm[jj] = NINF_F;
    #pragma unroll
    for (int i=0;i<4;i++) {
        int row = ty*4 + i;
        int cent = cent0 + (row >> 5);
        if (g_nbr1[cent*KNB + (row & 31)] >= 0) {
            #pragma unroll
            for (int jj=0;jj<8;jj++)
                pm[jj] = fmaxf(pm[jj], fmaxf(acc[i][jj] + b1b[tx*8+jj], 0.f));
        }
    }
    #pragma unroll
    for (int jj=0;jj<8;jj++) sA[ty*128 + tx*8 + jj] = pm[jj];
    __syncthreads();
    {
        int cent = t >> 7;
        int col  = t & 127;
        float v = NINF_F;
        #pragma unroll
        for (int g = 0; g < 8; g++)
            v = fmaxf(v, sA[(cent*8+g)*128 + col]);
        g_x1[(size_t)(cent0+cent)*128 + col] = v;
    }
}

// ---------------- gather / feature build (layers 2 & 3) --------------------
__global__ void k_gather2()
{
    int row = blockIdx.x*8 + (threadIdx.x >> 5);
    int lane = threadIdx.x & 31;
    if (row >= PNUM*M2c*KNB) return;
    int cent = row >> 5;
    int p = cent >> 7;
    int j = g_nbr2[row];
    float qx = g_q2[cent*3], qy = g_q2[cent*3+1], qz = g_q2[cent*3+2];
    for (int c = lane; c < 136; c += 32) {
        float v = 0.f;
        if (j >= 0) {
            if (c < 128)        v = g_x1[((size_t)(p*M1c + j))*128 + c];
            else if (c == 128)  v = __fadd_rn(g_q1[(p*M1c+j)*3+0], -qx);
            else if (c == 129)  v = __fadd_rn(g_q1[(p*M1c+j)*3+1], -qy);
            else if (c == 130)  v = __fadd_rn(g_q1[(p*M1c+j)*3+2], -qz);
        }
        g_feat[(size_t)row*136 + c] = v;
    }
}

__global__ void k_gather3(const float* __restrict__ out)
{
    int tid = blockIdx.x*256 + threadIdx.x;
    if (tid >= PNUM*M2c*392) return;
    int r = tid / 392, c = tid - r*392;
    float v = 0.f;
    if (c < 384)      v = out[OFF_X2 + (size_t)r*384 + c];
    else if (c < 387) v = g_q2[r*3 + (c-384)];
    g_feat[(size_t)r*392 + c] = v;
}

// ------- SGEMM: relu(A@W+b), 128x128 tile, BK=8, 8x8 micro, prefetched ----
__global__ void __launch_bounds__(256) k_gemm_relu(
    const float* __restrict__ A, const float* __restrict__ W,
    const float* __restrict__ bias, float* __restrict__ C,
    int M, int N, int K)
{
    __shared__ float As[8][128];
    __shared__ float Bs[8][128];
    const int ntile = N >> 7;
    const int bx = blockIdx.x % ntile;
    const int by = blockIdx.x / ntile;
    const int t = threadIdx.x;
    const int tx = t & 15, ty = t >> 4;
    const int row0 = by*128, col0 = bx*128;
    float acc[8][8] = {};
    const int ar = t >> 1, ac = (t & 1) * 4;
    const int br = t >> 5, bc = (t & 31) * 4;
    const float* Aptr = A + (size_t)(row0 + ar)*K + ac;
    const float* Wptr = W + (size_t)br*N + col0 + bc;
    float4 av = *(const float4*)(Aptr);
    float4 bv = *(const float4*)(Wptr);
    for (int k0 = 0; k0 < K; k0 += 8) {
        As[ac][ar] = av.x; As[ac+1][ar] = av.y; As[ac+2][ar] = av.z; As[ac+3][ar] = av.w;
        *(float4*)&Bs[br][bc] = bv;
        __syncthreads();
        if (k0 + 8 < K) {
            av = *(const float4*)(Aptr + k0 + 8);
            bv = *(const float4*)(Wptr + (size_t)(k0 + 8)*N);
        }
        #pragma unroll
        for (int kk = 0; kk < 8; kk++) {
            float4 a0 = *(const float4*)&As[kk][ty*8];
            float4 a1 = *(const float4*)&As[kk][ty*8 + 4];
            float4 b0 = *(const float4*)&Bs[kk][tx*8];
            float4 b1 = *(const float4*)&Bs[kk][tx*8 + 4];
            float aa[8] = {a0.x,a0.y,a0.z,a0.w,a1.x,a1.y,a1.z,a1.w};
            float bb[8] = {b0.x,b0.y,b0.z,b0.w,b1.x,b1.y,b1.z,b1.w};
            #pragma unroll
            for (int i = 0; i < 8; i++)
                #pragma unroll
                for (int jj = 0; jj < 8; jj++)
                    acc[i][jj] += aa[i]*bb[jj];
        }
        __syncthreads();
    }
    #pragma unroll
    for (int i = 0; i < 8; i++) {
        int r = row0 + ty*8 + i;
        float* crow = C + (size_t)r*N + col0 + tx*8;
        float4 o0, o1;
        o0.x = fmaxf(acc[i][0] + bias[col0+tx*8+0], 0.f);
        o0.y = fmaxf(acc[i][1] + bias[col0+tx*8+1], 0.f);
        o0.z = fmaxf(acc[i][2] + bias[col0+tx*8+2], 0.f);
        o0.w = fmaxf(acc[i][3] + bias[col0+tx*8+3], 0.f);
        o1.x = fmaxf(acc[i][4] + bias[col0+tx*8+4], 0.f);
        o1.y = fmaxf(acc[i][5] + bias[col0+tx*8+5], 0.f);
        o1.z = fmaxf(acc[i][6] + bias[col0+tx*8+6], 0.f);
        o1.w = fmaxf(acc[i][7] + bias[col0+tx*8+7], 0.f);
        *(float4*)crow = o0;
        *(float4*)(crow+4) = o1;
    }
}

// -- L2 second GEMM fused with masked neighbor-max, 128x128 tile ------------
__global__ void __launch_bounds__(256) k_gemm2_max(
    const float* __restrict__ A, const float* __restrict__ W,
    const float* __restrict__ bias, float* __restrict__ out)
{
    // M=262144, N=384, K=256; 128 rows = 4 centroids
    __shared__ float As[8][128];
    __shared__ float Bs[8][128];
    __shared__ float sS[16][128];
    const int ntile = 3;                      // 384/128
    const int bx = blockIdx.x % ntile;
    const int by = blockIdx.x / ntile;
    const int t = threadIdx.x;
    const int tx = t & 15, ty = t >> 4;
    const int row0 = by*128, col0 = bx*128;
    const int N = 384, K = 256;
    float acc[8][8] = {};
    const int ar = t >> 1, ac = (t & 1) * 4;
    const int br = t >> 5, bc = (t & 31) * 4;
    const float* Aptr = A + (size_t)(row0 + ar)*K + ac;
    const float* Wptr = W + (size_t)br*N + col0 + bc;
    float4 av = *(const float4*)(Aptr);
    float4 bv = *(const float4*)(Wptr);
    for (int k0 = 0; k0 < K; k0 += 8) {
        As[ac][ar] = av.x; As[ac+1][ar] = av.y; As[ac+2][ar] = av.z; As[ac+3][ar] = av.w;
        *(float4*)&Bs[br][bc] = bv;
        __syncthreads();
        if (k0 + 8 < K) {
            av = *(const float4*)(Aptr + k0 + 8);
            bv = *(const float4*)(Wptr + (size_t)(k0 + 8)*N);
        }
        #pragma unroll
        for (int kk = 0; kk < 8; kk++) {
            float4 a0 = *(const float4*)&As[kk][ty*8];
            float4 a1 = *(const float4*)&As[kk][ty*8 + 4];
            float4 b0 = *(const float4*)&Bs[kk][tx*8];
            float4 b1 = *(const float4*)&Bs[kk][tx*8 + 4];
            float aa[8] = {a0.x,a0.y,a0.z,a0.w,a1.x,a1.y,a1.z,a1.w};
            float bb[8] = {b0.x,b0.y,b0.z,b0.w,b1.x,b1.y,b1.z,b1.w};
            #pragma unroll
            for (int i = 0; i < 8; i++)
                #pragma unroll
                for (int jj = 0; jj < 8; jj++)
                    acc[i][jj] += aa[i]*bb[jj];
        }
        __syncthreads();
    }
    // per-thread masked max over its 8 rows (all inside one centroid: ty>>2)
    {
        const int gcent = by*4 + (ty >> 2);
        float pm[8];
        #pragma unroll
        for (int jj=0;jj<8;jj++) pm[jj] = NINF_F;
        #pragma unroll
        for (int i=0;i<8;i++) {
            int row = ty*8 + i;               // local row; row&31 = neighbor idx
            if (g_nbr2[gcent*KNB + (row & 31)] >= 0) {
                #pragma unroll
                for (int jj=0;jj<8;jj++)
                    pm[jj] = fmaxf(pm[jj], fmaxf(acc[i][jj] + bias[col0+tx*8+jj], 0.f));
            }
        }
        #pragma unroll
        for (int jj=0;jj<8;jj++) sS[ty][tx*8+jj] = pm[jj];
    }
    __syncthreads();
    #pragma unroll
    for (int o = 0; o < 2; o++) {
        int idx = t + o*256;                  // 512 outputs: 4 cents x 128 cols
        int centl = idx >> 7, col = idx & 127;
        float v = fmaxf(fmaxf(sS[centl*4+0][col], sS[centl*4+1][col]),
                        fmaxf(sS[centl*4+2][col], sS[centl*4+3][col]));
        out[OFF_X2 + (size_t)(by*4+centl)*384 + col0 + col] = v;
    }
}

// ---------------- global max over centroids (layer 3) ----------------------
__global__ void k_max3(float* __restrict__ out)
{
    int tid = blockIdx.x*256 + threadIdx.x;
    if (tid >= PNUM*768) return;
    int p = tid / 768, c = tid - p*768;
    float v = NINF_F;
    for (int m = 0; m < M2c; m++)
        v = fmaxf(v, g_hb[((size_t)p*M2c + m)*768 + c]);
    out[OFF_XG + tid] = v;
}

// ---------------- launcher --------------------------------------------------
static void launch_gemm(const float* A, const float* W, const float* b, float* C,
                        int M, int N, int K)
{
    int blocks = (M/128) * (N/128);
    k_gemm_relu<<<blocks, 256>>>(A, W, b, C, M, N, K);
}

extern "C" void kernel_launch(void* const* d_in, const int* in_sizes, int n_in,
                              void* d_out, int out_size)
{
    const float* pos = (const float*)d_in[0];
    const float* W1a = (const float*)d_in[2];
    const float* b1a = (const float*)d_in[3];
    const float* W1b = (const float*)d_in[4];
    const float* b1b = (const float*)d_in[5];
    const float* W2a = (const float*)d_in[6];
    const float* b2a = (const float*)d_in[7];
    const float* W2b = (const float*)d_in[8];
    const float* b2b = (const float*)d_in[9];
    const float* W3a = (const float*)d_in[10];
    const float* b3a = (const float*)d_in[11];
    const float* W3b = (const float*)d_in[12];
    const float* b3b = (const float*)d_in[13];
    float* out = (float*)d_out;

    float *pn, *q1, *q2, *feat, *h, *hb, *w2a, *w3a;
    int *nbr1, *nbr2;
    cudaGetSymbolAddress((void**)&pn,   g_pn);
    cudaGetSymbolAddress((void**)&q1,   g_q1);
    cudaGetSymbolAddress((void**)&q2,   g_q2);
    cudaGetSymbolAddress((void**)&feat, g_feat);
    cudaGetSymbolAddress((void**)&h,    g_h);
    cudaGetSymbolAddress((void**)&hb,   g_hb);
    cudaGetSymbolAddress((void**)&w2a,  g_w2a);
    cudaGetSymbolAddress((void**)&w3a,  g_w3a);
    cudaGetSymbolAddress((void**)&nbr1, g_nbr1);
    cudaGetSymbolAddress((void**)&nbr2, g_nbr2);

    // stage 0: normalize + constants + padded weights
    k_norm<<<PNUM, 256>>>(pos, out);
    k_aux<<<(392*512 + 255)/256, 256>>>(W2a, W3a, out);

    // layer 1: FPS -> radius top-K -> fused gather+MLP+max
    k_fps<NP1, M1c><<<PNUM, 256>>>(pn, q1, nullptr);
    k_select<NP1><<<PNUM*M1c/8, 256>>>(pn, q1, nbr1, 0.0225f, M1c);
    k_l1_fused<<<PNUM*M1c/2, 256>>>(W1a, b1a, W1b, b1b);

    // layer 2
    k_fps<M1c, M2c><<<PNUM, 256>>>(q1, q2, out + OFF_Q2);
    k_select<M1c><<<PNUM*M2c/8, 256>>>(q1, q2, nbr2, 0.09f, M2c);
    k_gather2<<<PNUM*M2c*KNB/8, 256>>>();
    launch_gemm(feat, w2a, b2a, h, PNUM*M2c*KNB, 256, 136);
    k_gemm2_max<<<(PNUM*M2c*KNB/128)*3, 256>>>(h, W2b, b2b, out);

    // layer 3
    k_gather3<<<(PNUM*M2c*392 + 255)/256, 256>>>(out);
    launch_gemm(feat, w3a, b3a, h,  PNUM*M2c, 512, 392);
    launch_gemm(h,    W3b, b3b, hb, PNUM*M2c, 768, 512);
    k_max3<<<(PNUM*768 + 255)/256, 256>>>(out);
}

// round 15
// speedup vs baseline: 1.1173x; 1.1116x over previous
#include <cuda_runtime.h>
#include <cstdint>
#include <cstddef>

// ---------------- problem constants ----------------
#define PNUM 64
#define NP1  2048
#define M1c  512
#define M2c  128
#define KNB  32

#define INF_F  __int_as_float(0x7f800000)
#define NINF_F __int_as_float(0xff800000)

// ---------------- output layout (float32 concat of reference tuple) -------
#define OFF_XG      0          // 64*768
#define OFF_POSG    49152      // 64*3
#define OFF_BATCHG  49344      // 64
#define OFF_X2      49408      // 8192*384
#define OFF_Q2      3195136    // 8192*3
#define OFF_BATCH2  3219712    // 8192
#define OFF_VMIN    3227904    // 64*3
#define OFF_DIFF    3228096    // 64  (total 3228160)

// ---------------- scratch (__device__ globals; allocation-guard safe) -----
__device__ float g_pn  [PNUM*NP1*3];
__device__ float g_q1  [PNUM*M1c*3];
__device__ float g_q2  [PNUM*M2c*3];
__device__ int   g_nbr1[PNUM*M1c*KNB];
__device__ int   g_nbr2[PNUM*M2c*KNB];
__device__ float g_x1  [PNUM*M1c*128];
__device__ float g_feat[PNUM*M2c*KNB*136];   // u (L2, 32768*256) ; L3 feat reuses
__device__ float g_h   [PNUM*M2c*KNB*256];   // L2 hidden; L3 reuses
__device__ float g_hb  [PNUM*M2c*768];       // L3 final pre-max
__device__ float g_w2a [136*256];
__device__ float g_w3a [392*512];

// exact (non-fma) squared distance, matching XLA's ((dx^2+dy^2)+dz^2)
__device__ __forceinline__ float d2f(float ax,float ay,float az,float bx,float by,float bz){
    float dx=__fadd_rn(ax,-bx), dy=__fadd_rn(ay,-by), dz=__fadd_rn(az,-bz);
    return __fadd_rn(__fadd_rn(__fmul_rn(dx,dx),__fmul_rn(dy,dy)),__fmul_rn(dz,dz));
}

// ---------------- normalize: per-patch min/max, pn = (p - vmin)/diff -------
__global__ void k_norm(const float* __restrict__ pos, float* __restrict__ out)
{
    const int p = blockIdx.x, t = threadIdx.x;
    __shared__ float smn[3*256], smx[3*256];
    __shared__ float svm[3]; __shared__ float sdf;
    float mn0=INF_F, mn1=INF_F, mn2=INF_F, mx0=NINF_F, mx1=NINF_F, mx2=NINF_F;
    const float* pp = pos + (size_t)p * NP1 * 3;
    for (int i = t; i < NP1; i += 256) {
        float x = pp[i*3+0], y = pp[i*3+1], z = pp[i*3+2];
        mn0 = fminf(mn0,x); mn1 = fminf(mn1,y); mn2 = fminf(mn2,z);
        mx0 = fmaxf(mx0,x); mx1 = fmaxf(mx1,y); mx2 = fmaxf(mx2,z);
    }
    smn[t]=mn0; smn[256+t]=mn1; smn[512+t]=mn2;
    smx[t]=mx0; smx[256+t]=mx1; smx[512+t]=mx2;
    __syncthreads();
    for (int s = 128; s > 0; s >>= 1) {
        if (t < s) {
            #pragma unroll
            for (int c = 0; c < 3; c++) {
                smn[c*256+t] = fminf(smn[c*256+t], smn[c*256+t+s]);
                smx[c*256+t] = fmaxf(smx[c*256+t], smx[c*256+t+s]);
            }
        }
        __syncthreads();
    }
    if (t == 0) {
        float d0 = smx[0]-smn[0], d1 = smx[256]-smn[256], d2 = smx[512]-smn[512];
        float df = fmaxf(d0, fmaxf(d1, d2));
        svm[0]=smn[0]; svm[1]=smn[256]; svm[2]=smn[512]; sdf = df;
        out[OFF_VMIN + p*3+0] = smn[0];
        out[OFF_VMIN + p*3+1] = smn[256];
        out[OFF_VMIN + p*3+2] = smn[512];
        out[OFF_DIFF + p] = df;
    }
    __syncthreads();
    const float vx=svm[0], vy=svm[1], vz=svm[2], df=sdf;
    for (int i = t; i < NP1; i += 256) {
        size_t b = ((size_t)p*NP1 + i)*3;
        g_pn[b+0] = __fdiv_rn(__fadd_rn(pp[i*3+0],-vx), df);
        g_pn[b+1] = __fdiv_rn(__fadd_rn(pp[i*3+1],-vy), df);
        g_pn[b+2] = __fdiv_rn(__fadd_rn(pp[i*3+2],-vz), df);
    }
}

// ---------------- aux: pad weights, write constant output regions ----------
__global__ void k_aux(const float* __restrict__ W2a, const float* __restrict__ W3a,
                      float* __restrict__ out)
{
    int tid = blockIdx.x*256 + threadIdx.x;
    if (tid < 136*256)  g_w2a[tid] = (tid < 131*256) ? W2a[tid] : 0.f;
    if (tid < 392*512)  g_w3a[tid] = (tid < 387*512) ? W3a[tid] : 0.f;
    if (tid < 192)      out[OFF_POSG + tid] = 0.f;
    if (tid < 64)       out[OFF_BATCHG + tid] = (float)tid;
    if (tid < PNUM*M2c) out[OFF_BATCH2 + tid] = (float)(tid / M2c);
}

// ---------------- FPS (sequential, shared-memory resident) -----------------
template<int NP, int MS>
__global__ void k_fps(const float* __restrict__ pts,
                      float* __restrict__ q_out, float* __restrict__ q_out2)
{
    const int p = blockIdx.x, t = threadIdx.x;
    const int lane = t & 31, wid = t >> 5;
    __shared__ float sx[NP], sy[NP], sz[NP], sd[NP];
    __shared__ float rv[8]; __shared__ int ri[8];
    __shared__ int ssel[MS]; __shared__ int sj;
    const float* pp = pts + (size_t)p * NP * 3;
    for (int i = t; i < NP; i += 256) { sx[i]=pp[i*3]; sy[i]=pp[i*3+1]; sz[i]=pp[i*3+2]; }
    __syncthreads();
    const float x0 = sx[0], y0 = sy[0], z0 = sz[0];
    for (int i = t; i < NP; i += 256)
        sd[i] = d2f(sx[i],sy[i],sz[i], x0,y0,z0);
    if (t == 0) ssel[0] = 0;
    __syncthreads();
    for (int s = 1; s < MS; s++) {
        float bv = -1.0f; int bi = 0;
        for (int i = t; i < NP; i += 256) { float v = sd[i]; if (v > bv) { bv = v; bi = i; } }
        #pragma unroll
        for (int o = 16; o > 0; o >>= 1) {
            float ov = __shfl_down_sync(0xffffffffu, bv, o);
            int   oi = __shfl_down_sync(0xffffffffu, bi, o);
            if (ov > bv || (ov == bv && oi < bi)) { bv = ov; bi = oi; }
        }
        if (lane == 0) { rv[wid] = bv; ri[wid] = bi; }
        __syncthreads();
        if (t == 0) {
            float v = rv[0]; int b = ri[0];
            #pragma unroll
            for (int w = 1; w < 8; w++)
                if (rv[w] > v || (rv[w] == v && ri[w] < b)) { v = rv[w]; b = ri[w]; }
            sj = b; ssel[s] = b;
        }
        __syncthreads();
        const int j = sj;
        const float jx = sx[j], jy = sy[j], jz = sz[j];
        for (int i = t; i < NP; i += 256)
            sd[i] = fminf(sd[i], d2f(sx[i],sy[i],sz[i], jx,jy,jz));
        __syncthreads();
    }
    for (int m = t; m < MS; m += 256) {
        int j = ssel[m];
        size_t qb = ((size_t)p*MS + m)*3;
        float qx=sx[j], qy=sy[j], qz=sz[j];
        q_out[qb+0]=qx; q_out[qb+1]=qy; q_out[qb+2]=qz;
        if (q_out2) { q_out2[qb+0]=qx; q_out2[qb+1]=qy; q_out2[qb+2]=qz; }
    }
}

// ---------------- warp top-K(32) within radius, bitonic merge --------------
__device__ __forceinline__ bool pless(float d, int i, float od, int oi)
{
    return d < od || (d == od && i < oi);
}

template<int NP>
__global__ void k_select(const float* __restrict__ pts, const float* __restrict__ q,
                         int* __restrict__ nbr, float r2, int M)
{
    const int grpPerPatch = M / 8;
    const int p   = blockIdx.x / grpPerPatch;
    const int grp = blockIdx.x % grpPerPatch;
    const int t = threadIdx.x, lane = t & 31, w = t >> 5;
    __shared__ float sx[NP], sy[NP], sz[NP];
    const float* pp = pts + (size_t)p * NP * 3;
    for (int i = t; i < NP; i += 256) { sx[i]=pp[i*3]; sy[i]=pp[i*3+1]; sz[i]=pp[i*3+2]; }
    __syncthreads();
    const int m = grp*8 + w;
    const int cent = p*M + m;
    const float qx = q[cent*3], qy = q[cent*3+1], qz = q[cent*3+2];
    float cd = INF_F; int ci = 0x7fffff00 + lane;   // (inf, big distinct idx) pads, asc
    for (int nb = 0; nb < NP/32; nb++) {
        const int j = nb*32 + lane;
        float d2 = d2f(sx[j],sy[j],sz[j], qx,qy,qz);
        float nd = (d2 <= r2) ? d2 : INF_F;
        int   ni = j;
        float td = __shfl_sync(0xffffffffu, cd, 31);
        if (__any_sync(0xffffffffu, nd < td)) {
            #pragma unroll
            for (int size = 2; size <= 32; size <<= 1) {
                #pragma unroll
                for (int stride = size >> 1; stride > 0; stride >>= 1) {
                    float od = __shfl_xor_sync(0xffffffffu, nd, stride);
                    int   oi = __shfl_xor_sync(0xffffffffu, ni, stride);
                    bool up    = ((lane & size) == 0);
                    bool lower = ((lane & stride) == 0);
                    bool ls = pless(nd, ni, od, oi);
                    bool take = (lower == up) ? !ls : ls;
                    if (take) { nd = od; ni = oi; }
                }
            }
            float rd = __shfl_sync(0xffffffffu, nd, 31 - lane);
            int   rx = __shfl_sync(0xffffffffu, ni, 31 - lane);
            if (pless(rd, rx, cd, ci)) { cd = rd; ci = rx; }
            #pragma unroll
            for (int stride = 16; stride > 0; stride >>= 1) {
                float od = __shfl_xor_sync(0xffffffffu, cd, stride);
                int   oi = __shfl_xor_sync(0xffffffffu, ci, stride);
                bool lower = ((lane & stride) == 0);
                bool ls = pless(cd, ci, od, oi);
                bool take = lower ? !ls : ls;
                if (take) { cd = od; ci = oi; }
            }
        }
    }
    nbr[cent*KNB + lane] = (cd <= r2) ? ci : -1;
}

// ---------------- fused layer 1: gather + MLP(6->64->128) + masked max -----
__global__ void __launch_bounds__(256) k_l1_fused(
    const float* __restrict__ W1a, const float* __restrict__ b1a,
    const float* __restrict__ W1b, const float* __restrict__ b1b)
{
    __shared__ float sW[64*128];   // W1b, 32KB
    __shared__ float sA[64*64];    // h1 [k][row], 16KB (reused for partials)
    const int t = threadIdx.x;
    const int cent0 = blockIdx.x * 2;
    const int p = cent0 >> 9;
    {
        const float4* wsrc = (const float4*)W1b;
        float4* wdst = (float4*)sW;
        #pragma unroll
        for (int i = 0; i < 8; i++) wdst[t + i*256] = wsrc[t + i*256];
    }
    {
        const int row = t >> 2;
        const int c0 = (t & 3) * 16;
        const int cent = cent0 + (row >> 5);
        const int j = g_nbr1[cent*KNB + (row & 31)];
        float f0=0,f1=0,f2=0,f3=0,f4=0,f5=0;
        if (j >= 0) {
            size_t pb = ((size_t)p*NP1 + j)*3;
            f0 = g_pn[pb]; f1 = g_pn[pb+1]; f2 = g_pn[pb+2];
            f3 = __fadd_rn(f0, -g_q1[cent*3]);
            f4 = __fadd_rn(f1, -g_q1[cent*3+1]);
            f5 = __fadd_rn(f2, -g_q1[cent*3+2]);
        }
        #pragma unroll
        for (int c = 0; c < 16; c++) {
            float acc = b1a[c0+c];
            acc += f0*W1a[0*64+c0+c]; acc += f1*W1a[1*64+c0+c];
            acc += f2*W1a[2*64+c0+c]; acc += f3*W1a[3*64+c0+c];
            acc += f4*W1a[4*64+c0+c]; acc += f5*W1a[5*64+c0+c];
            sA[(c0+c)*64 + row] = fmaxf(acc, 0.f);
        }
    }
    __syncthreads();
    const int tx = t & 15, ty = t >> 4;
    float acc[4][8] = {};
    #pragma unroll 4
    for (int k = 0; k < 64; k++) {
        float4 a  = *(const float4*)&sA[k*64 + ty*4];
        float4 b0 = *(const float4*)&sW[k*128 + tx*8];
        float4 b1 = *(const float4*)&sW[k*128 + tx*8 + 4];
        float av[4] = {a.x,a.y,a.z,a.w};
        float bv[8] = {b0.x,b0.y,b0.z,b0.w,b1.x,b1.y,b1.z,b1.w};
        #pragma unroll
        for (int i=0;i<4;i++)
            #pragma unroll
            for (int jj=0;jj<8;jj++)
                acc[i][jj] += av[i]*bv[jj];
    }
    __syncthreads();
    float pm[8];
    #pragma unroll
    for (int jj=0;jj<8;jj++) pm[jj] = NINF_F;
    #pragma unroll
    for (int i=0;i<4;i++) {
        int row = ty*4 + i;
        int cent = cent0 + (row >> 5);
        if (g_nbr1[cent*KNB + (row & 31)] >= 0) {
            #pragma unroll
            for (int jj=0;jj<8;jj++)
                pm[jj] = fmaxf(pm[jj], fmaxf(acc[i][jj] + b1b[tx*8+jj], 0.f));
        }
    }
    #pragma unroll
    for (int jj=0;jj<8;jj++) sA[ty*128 + tx*8 + jj] = pm[jj];
    __syncthreads();
    {
        int cent = t >> 7;
        int col  = t & 127;
        float v = NINF_F;
        #pragma unroll
        for (int g = 0; g < 8; g++)
            v = fmaxf(v, sA[(cent*8+g)*128 + col]);
        g_x1[(size_t)(cent0+cent)*128 + col] = v;
    }
}

// ------- h build for layer 2: h[row] = relu(u[j] + (pj-q)·W2a[128:131] + b)
__global__ void __launch_bounds__(256) k_hbuild(const float* __restrict__ u,
                                               const float* __restrict__ b2a)
{
    __shared__ float sw0[256], sw1[256], sw2[256], sb[256];
    const int t = threadIdx.x;
    sw0[t] = g_w2a[128*256 + t];
    sw1[t] = g_w2a[129*256 + t];
    sw2[t] = g_w2a[130*256 + t];
    sb[t]  = b2a[t];
    __syncthreads();
    const int row = blockIdx.x*8 + (t >> 5);       // [0, 262144)
    const int lane = t & 31;
    const int cent = row >> 5;
    const int p = cent >> 7;
    const int j = g_nbr2[row];
    float f0=0.f, f1=0.f, f2=0.f;
    const float* urow = u;                          // dummy; guarded by j>=0
    if (j >= 0) {
        int gj = p*M1c + j;
        f0 = __fadd_rn(g_q1[gj*3+0], -g_q2[cent*3+0]);
        f1 = __fadd_rn(g_q1[gj*3+1], -g_q2[cent*3+1]);
        f2 = __fadd_rn(g_q1[gj*3+2], -g_q2[cent*3+2]);
        urow = u + (size_t)gj*256;
    }
    float* hrow = g_h + (size_t)row*256;
    #pragma unroll
    for (int i = 0; i < 8; i++) {
        int c = lane + i*32;
        float acc = (j >= 0) ? urow[c] : 0.f;
        acc = __fmaf_rn(f0, sw0[c], acc);
        acc = __fmaf_rn(f1, sw1[c], acc);
        acc = __fmaf_rn(f2, sw2[c], acc);
        hrow[c] = fmaxf(acc + sb[c], 0.f);
    }
}

__global__ void k_gather3(const float* __restrict__ out)
{
    int tid = blockIdx.x*256 + threadIdx.x;
    if (tid >= PNUM*M2c*392) return;
    int r = tid / 392, c = tid - r*392;
    float v = 0.f;
    if (c < 384)      v = out[OFF_X2 + (size_t)r*384 + c];
    else if (c < 387) v = g_q2[r*3 + (c-384)];
    g_feat[(size_t)r*392 + c] = v;
}

// ------- SGEMM: relu(A@W+b), 128x128 tile, BK=8, 8x8 micro, prefetched ----
__global__ void __launch_bounds__(256) k_gemm_relu(
    const float* __restrict__ A, const float* __restrict__ W,
    const float* __restrict__ bias, float* __restrict__ C,
    int M, int N, int K)
{
    __shared__ float As[8][128];
    __shared__ float Bs[8][128];
    const int ntile = N >> 7;
    const int bx = blockIdx.x % ntile;
    const int by = blockIdx.x / ntile;
    const int t = threadIdx.x;
    const int tx = t & 15, ty = t >> 4;
    const int row0 = by*128, col0 = bx*128;
    float acc[8][8] = {};
    const int ar = t >> 1, ac = (t & 1) * 4;
    const int br = t >> 5, bc = (t & 31) * 4;
    const float* Aptr = A + (size_t)(row0 + ar)*K + ac;
    const float* Wptr = W + (size_t)br*N + col0 + bc;
    float4 av = *(const float4*)(Aptr);
    float4 bv = *(const float4*)(Wptr);
    for (int k0 = 0; k0 < K; k0 += 8) {
        As[ac][ar] = av.x; As[ac+1][ar] = av.y; As[ac+2][ar] = av.z; As[ac+3][ar] = av.w;
        *(float4*)&Bs[br][bc] = bv;
        __syncthreads();
        if (k0 + 8 < K) {
            av = *(const float4*)(Aptr + k0 + 8);
            bv = *(const float4*)(Wptr + (size_t)(k0 + 8)*N);
        }
        #pragma unroll
        for (int kk = 0; kk < 8; kk++) {
            float4 a0 = *(const float4*)&As[kk][ty*8];
            float4 a1 = *(const float4*)&As[kk][ty*8 + 4];
            float4 b0 = *(const float4*)&Bs[kk][tx*8];
            float4 b1 = *(const float4*)&Bs[kk][tx*8 + 4];
            float aa[8] = {a0.x,a0.y,a0.z,a0.w,a1.x,a1.y,a1.z,a1.w};
            float bb[8] = {b0.x,b0.y,b0.z,b0.w,b1.x,b1.y,b1.z,b1.w};
            #pragma unroll
            for (int i = 0; i < 8; i++)
                #pragma unroll
                for (int jj = 0; jj < 8; jj++)
                    acc[i][jj] += aa[i]*bb[jj];
        }
        __syncthreads();
    }
    #pragma unroll
    for (int i = 0; i < 8; i++) {
        int r = row0 + ty*8 + i;
        float* crow = C + (size_t)r*N + col0 + tx*8;
        float4 o0, o1;
        o0.x = fmaxf(acc[i][0] + bias[col0+tx*8+0], 0.f);
        o0.y = fmaxf(acc[i][1] + bias[col0+tx*8+1], 0.f);
        o0.z = fmaxf(acc[i][2] + bias[col0+tx*8+2], 0.f);
        o0.w = fmaxf(acc[i][3] + bias[col0+tx*8+3], 0.f);
        o1.x = fmaxf(acc[i][4] + bias[col0+tx*8+4], 0.f);
        o1.y = fmaxf(acc[i][5] + bias[col0+tx*8+5], 0.f);
        o1.z = fmaxf(acc[i][6] + bias[col0+tx*8+6], 0.f);
        o1.w = fmaxf(acc[i][7] + bias[col0+tx*8+7], 0.f);
        *(float4*)crow = o0;
        *(float4*)(crow+4) = o1;
    }
}

// ------- plain SGEMM (no bias, no relu): u = A @ W, 128x128 tile ----------
__global__ void __launch_bounds__(256) k_gemm_plain(
    const float* __restrict__ A, const float* __restrict__ W,
    float* __restrict__ C, int M, int N, int K)
{
    __shared__ float As[8][128];
    __shared__ float Bs[8][128];
    const int ntile = N >> 7;
    const int bx = blockIdx.x % ntile;
    const int by = blockIdx.x / ntile;
    const int t = threadIdx.x;
    const int tx = t & 15, ty = t >> 4;
    const int row0 = by*128, col0 = bx*128;
    float acc[8][8] = {};
    const int ar = t >> 1, ac = (t & 1) * 4;
    const int br = t >> 5, bc = (t & 31) * 4;
    const float* Aptr = A + (size_t)(row0 + ar)*K + ac;
    const float* Wptr = W + (size_t)br*N + col0 + bc;
    float4 av = *(const float4*)(Aptr);
    float4 bv = *(const float4*)(Wptr);
    for (int k0 = 0; k0 < K; k0 += 8) {
        As[ac][ar] = av.x; As[ac+1][ar] = av.y; As[ac+2][ar] = av.z; As[ac+3][ar] = av.w;
        *(float4*)&Bs[br][bc] = bv;
        __syncthreads();
        if (k0 + 8 < K) {
            av = *(const float4*)(Aptr + k0 + 8);
            bv = *(const float4*)(Wptr + (size_t)(k0 + 8)*N);
        }
        #pragma unroll
        for (int kk = 0; kk < 8; kk++) {
            float4 a0 = *(const float4*)&As[kk][ty*8];
            float4 a1 = *(const float4*)&As[kk][ty*8 + 4];
            float4 b0 = *(const float4*)&Bs[kk][tx*8];
            float4 b1 = *(const float4*)&Bs[kk][tx*8 + 4];
            float aa[8] = {a0.x,a0.y,a0.z,a0.w,a1.x,a1.y,a1.z,a1.w};
            float bb[8] = {b0.x,b0.y,b0.z,b0.w,b1.x,b1.y,b1.z,b1.w};
            #pragma unroll
            for (int i = 0; i < 8; i++)
                #pragma unroll
                for (int jj = 0; jj < 8; jj++)
                    acc[i][jj] += aa[i]*bb[jj];
        }
        __syncthreads();
    }
    #pragma unroll
    for (int i = 0; i < 8; i++) {
        int r = row0 + ty*8 + i;
        float* crow = C + (size_t)r*N + col0 + tx*8;
        *(float4*)crow     = make_float4(acc[i][0], acc[i][1], acc[i][2], acc[i][3]);
        *(float4*)(crow+4) = make_float4(acc[i][4], acc[i][5], acc[i][6], acc[i][7]);
    }
}

// -- L2 second GEMM fused with masked neighbor-max, 128x128 tile ------------
__global__ void __launch_bounds__(256) k_gemm2_max(
    const float* __restrict__ A, const float* __restrict__ W,
    const float* __restrict__ bias, float* __restrict__ out)
{
    // M=262144, N=384, K=256; 128 rows = 4 centroids
    __shared__ float As[8][128];
    __shared__ float Bs[8][128];
    __shared__ float sS[16][128];
    const int ntile = 3;                      // 384/128
    const int bx = blockIdx.x % ntile;
    const int by = blockIdx.x / ntile;
    const int t = threadIdx.x;
    const int tx = t & 15, ty = t >> 4;
    const int row0 = by*128, col0 = bx*128;
    const int N = 384, K = 256;
    float acc[8][8] = {};
    const int ar = t >> 1, ac = (t & 1) * 4;
    const int br = t >> 5, bc = (t & 31) * 4;
    const float* Aptr = A + (size_t)(row0 + ar)*K + ac;
    const float* Wptr = W + (size_t)br*N + col0 + bc;
    float4 av = *(const float4*)(Aptr);
    float4 bv = *(const float4*)(Wptr);
    for (int k0 = 0; k0 < K; k0 += 8) {
        As[ac][ar] = av.x; As[ac+1][ar] = av.y; As[ac+2][ar] = av.z; As[ac+3][ar] = av.w;
        *(float4*)&Bs[br][bc] = bv;
        __syncthreads();
        if (k0 + 8 < K) {
            av = *(const float4*)(Aptr + k0 + 8);
            bv = *(const float4*)(Wptr + (size_t)(k0 + 8)*N);
        }
        #pragma unroll
        for (int kk = 0; kk < 8; kk++) {
            float4 a0 = *(const float4*)&As[kk][ty*8];
            float4 a1 = *(const float4*)&As[kk][ty*8 + 4];
            float4 b0 = *(const float4*)&Bs[kk][tx*8];
            float4 b1 = *(const float4*)&Bs[kk][tx*8 + 4];
            float aa[8] = {a0.x,a0.y,a0.z,a0.w,a1.x,a1.y,a1.z,a1.w};
            float bb[8] = {b0.x,b0.y,b0.z,b0.w,b1.x,b1.y,b1.z,b1.w};
            #pragma unroll
            for (int i = 0; i < 8; i++)
                #pragma unroll
                for (int jj = 0; jj < 8; jj++)
                    acc[i][jj] += aa[i]*bb[jj];
        }
        __syncthreads();
    }
    // per-thread masked max over its 8 rows (all inside one centroid: ty>>2)
    {
        const int gcent = by*4 + (ty >> 2);
        float pm[8];
        #pragma unroll
        for (int jj=0;jj<8;jj++) pm[jj] = NINF_F;
        #pragma unroll
        for (int i=0;i<8;i++) {
            int row = ty*8 + i;               // local row; row&31 = neighbor idx
            if (g_nbr2[gcent*KNB + (row & 31)] >= 0) {
                #pragma unroll
                for (int jj=0;jj<8;jj++)
                    pm[jj] = fmaxf(pm[jj], fmaxf(acc[i][jj] + bias[col0+tx*8+jj], 0.f));
            }
        }
        #pragma unroll
        for (int jj=0;jj<8;jj++) sS[ty][tx*8+jj] = pm[jj];
    }
    __syncthreads();
    #pragma unroll
    for (int o = 0; o < 2; o++) {
        int idx = t + o*256;                  // 512 outputs: 4 cents x 128 cols
        int centl = idx >> 7, col = idx & 127;
        float v = fmaxf(fmaxf(sS[centl*4+0][col], sS[centl*4+1][col]),
                        fmaxf(sS[centl*4+2][col], sS[centl*4+3][col]));
        out[OFF_X2 + (size_t)(by*4+centl)*384 + col0 + col] = v;
    }
}

// ---------------- global max over centroids (layer 3) ----------------------
__global__ void k_max3(float* __restrict__ out)
{
    int tid = blockIdx.x*256 + threadIdx.x;
    if (tid >= PNUM*768) return;
    int p = tid / 768, c = tid - p*768;
    float v = NINF_F;
    for (int m = 0; m < M2c; m++)
        v = fmaxf(v, g_hb[((size_t)p*M2c + m)*768 + c]);
    out[OFF_XG + tid] = v;
}

// ---------------- launcher --------------------------------------------------
static void launch_gemm(const float* A, const float* W, const float* b, float* C,
                        int M, int N, int K)
{
    int blocks = (M/128) * (N/128);
    k_gemm_relu<<<blocks, 256>>>(A, W, b, C, M, N, K);
}

extern "C" void kernel_launch(void* const* d_in, const int* in_sizes, int n_in,
                              void* d_out, int out_size)
{
    const float* pos = (const float*)d_in[0];
    const float* W1a = (const float*)d_in[2];
    const float* b1a = (const float*)d_in[3];
    const float* W1b = (const float*)d_in[4];
    const float* b1b = (const float*)d_in[5];
    const float* W2a = (const float*)d_in[6];
    const float* b2a = (const float*)d_in[7];
    const float* W2b = (const float*)d_in[8];
    const float* b2b = (const float*)d_in[9];
    const float* W3a = (const float*)d_in[10];
    const float* b3a = (const float*)d_in[11];
    const float* W3b = (const float*)d_in[12];
    const float* b3b = (const float*)d_in[13];
    float* out = (float*)d_out;

    float *pn, *q1, *q2, *x1, *feat, *h, *hb, *w2a, *w3a;
    int *nbr1, *nbr2;
    cudaGetSymbolAddress((void**)&pn,   g_pn);
    cudaGetSymbolAddress((void**)&q1,   g_q1);
    cudaGetSymbolAddress((void**)&q2,   g_q2);
    cudaGetSymbolAddress((void**)&x1,   g_x1);
    cudaGetSymbolAddress((void**)&feat, g_feat);
    cudaGetSymbolAddress((void**)&h,    g_h);
    cudaGetSymbolAddress((void**)&hb,   g_hb);
    cudaGetSymbolAddress((void**)&w2a,  g_w2a);
    cudaGetSymbolAddress((void**)&w3a,  g_w3a);
    cudaGetSymbolAddress((void**)&nbr1, g_nbr1);
    cudaGetSymbolAddress((void**)&nbr2, g_nbr2);

    // stage 0: normalize + constants + padded weights
    k_norm<<<PNUM, 256>>>(pos, out);
    k_aux<<<(392*512 + 255)/256, 256>>>(W2a, W3a, out);

    // layer 1: FPS -> radius top-K -> fused gather+MLP+max
    k_fps<NP1, M1c><<<PNUM, 256>>>(pn, q1, nullptr);
    k_select<NP1><<<PNUM*M1c/8, 256>>>(pn, q1, nbr1, 0.0225f, M1c);
    k_l1_fused<<<PNUM*M1c/2, 256>>>(W1a, b1a, W1b, b1b);

    // layer 2: factor feat@W2a = x1@W2a[:128] (per-point u) + (pj-q)@W2a[128:131]
    k_gemm_plain<<<(PNUM*M1c/128)*(256/128), 256>>>(x1, w2a, feat, PNUM*M1c, 256, 128);
    k_fps<M1c, M2c><<<PNUM, 256>>>(q1, q2, out + OFF_Q2);
    k_select<M1c><<<PNUM*M2c/8, 256>>>(q1, q2, nbr2, 0.09f, M2c);
    k_hbuild<<<PNUM*M2c*KNB/8, 256>>>(feat, b2a);
    k_gemm2_max<<<(PNUM*M2c*KNB/128)*3, 256>>>(h, W2b, b2b, out);

    // layer 3
    k_gather3<<<(PNUM*M2c*392 + 255)/256, 256>>>(out);
    launch_gemm(feat, w3a, b3a, h,  PNUM*M2c, 512, 392);
    launch_gemm(h,    W3b, b3b, hb, PNUM*M2c, 768, 512);
    k_max3<<<(PNUM*768 + 255)/256, 256>>>(out);
}